// round 2
// baseline (speedup 1.0000x reference)
#include <cuda_runtime.h>

// ---------------------------------------------------------------------------
// G2Conv2d4: per-quadrant energy argmax -> one-hot guided rect-cummax pool
//            -> 3x3 SAME conv.
// Key: guide is one-hot, so the guided directional pool collapses to
//   pooled[c,i,j] = (in quadrant rectangle) ? max(x^2, x^2[landmark]) : x^2
// Pooling is fused into the conv input loader; no intermediate tensor.
// Shapes: x[16,256,64,64] f32, w[256,256,3,3], bias[256], out[16,256,64,64].
// ---------------------------------------------------------------------------

__device__ int g_land[64];   // flattened argmax pixel per (b*4 + q)

// ---------------- Kernel 1: per-(b,q) energy argmax ----------------
__global__ void energy_argmax_kernel(const float* __restrict__ x) {
    int bq = blockIdx.x;
    int b = bq >> 2, q = bq & 3;
    const float* xb = x + (((size_t)b * 256 + q * 64) << 12);  // * 4096

    float best = -1.0f;
    int bidx = 0x7fffffff;
    for (int p = threadIdx.x; p < 4096; p += 256) {
        float s = 0.0f;
#pragma unroll 8
        for (int c = 0; c < 64; ++c) {
            float v = xb[((size_t)c << 12) + p];
            s = fmaf(v, v, s);
        }
        if (s > best) { best = s; bidx = p; }   // ascending p => first-max kept
    }

    __shared__ float sv[256];
    __shared__ int   si[256];
    sv[threadIdx.x] = best;
    si[threadIdx.x] = bidx;
    __syncthreads();
    for (int off = 128; off; off >>= 1) {
        if (threadIdx.x < off) {
            float ov = sv[threadIdx.x + off];
            int   oi = si[threadIdx.x + off];
            float mv = sv[threadIdx.x];
            int   mi = si[threadIdx.x];
            if (ov > mv || (ov == mv && oi < mi)) {
                sv[threadIdx.x] = ov;
                si[threadIdx.x] = oi;
            }
        }
        __syncthreads();
    }
    if (threadIdx.x == 0) g_land[bq] = si[0];
}

// ---------------- Kernel 2: fused pool + 3x3 conv ----------------
// Block: 64 output channels x 16x16 spatial tile, one batch.
// Threads: 256. Per-thread register tile: 8 co x 8 px (one half-row).
// K-loop over input channels in chunks of CK through shared memory.
#define CK 4

__global__ __launch_bounds__(256, 2)
void conv_pool_kernel(const float* __restrict__ x,
                      const float* __restrict__ w,
                      const float* __restrict__ bias,
                      float* __restrict__ out) {
    __shared__ float in_s[CK][18][18];
    __shared__ float w_s[CK][9][64];
    __shared__ float land_v[256];
    __shared__ int   land_r[4], land_c[4];

    const int tid = threadIdx.x;
    const int b = blockIdx.z;
    const int co_base = blockIdx.y * 64;
    const int s = blockIdx.x;
    const int ty0 = (s >> 2) << 4;
    const int tx0 = (s & 3) << 4;

    const float* xb = x + ((size_t)b << 20);   // b * 256*64*64

    // landmark coords + per-channel landmark values (x^2 at landmark)
    if (tid < 4) {
        int idx = g_land[b * 4 + tid];
        land_r[tid] = idx >> 6;
        land_c[tid] = idx & 63;
    }
    __syncthreads();
    {
        int ci = tid;                    // 256 threads == 256 channels
        int q = ci >> 6;
        float v = xb[((size_t)ci << 12) + (land_r[q] << 6) + land_c[q]];
        land_v[ci] = v * v;
    }
    __syncthreads();

    const int tco  = tid >> 5;           // 0..7  (co sub-tile)
    const int lane = tid & 31;
    const int py   = lane >> 1;          // 0..15 (row in tile)
    const int px0  = (lane & 1) << 3;    // 0 or 8 (col base)

    float acc[8][8];
#pragma unroll
    for (int k = 0; k < 8; ++k)
#pragma unroll
        for (int j = 0; j < 8; ++j) acc[k][j] = 0.0f;

    for (int ci0 = 0; ci0 < 256; ci0 += CK) {
        // ---- load weight chunk: w_s[ci_l][tap][co] ----
        {
            int co   = co_base + (tid & 63);
            int ci_l = tid >> 6;         // 0..3
            const float* wp = w + ((size_t)co * 256 + ci0 + ci_l) * 9;
#pragma unroll
            for (int t = 0; t < 9; ++t)
                w_s[ci_l][t][tid & 63] = wp[t];
        }
        // ---- load input patch with fused guided pool ----
        for (int idx = tid; idx < CK * 324; idx += 256) {
            int ci_l = idx / 324;
            int rem  = idx - ci_l * 324;
            int i    = rem / 18;
            int j    = rem - i * 18;
            int y    = ty0 + i - 1;
            int xx   = tx0 + j - 1;
            float p = 0.0f;              // SAME padding => 0
            if ((unsigned)y < 64u && (unsigned)xx < 64u) {
                int ci = ci0 + ci_l;
                float v = xb[((size_t)ci << 12) + (y << 6) + xx];
                p = v * v;
                int q = ci >> 6;
                int r = land_r[q], c = land_c[q];
                // _DIRS: q0(T,T): y<=r,x<=c  q1(T,F): y<=r,x>=c
                //        q2(F,T): y>=r,x<=c  q3(F,F): y>=r,x>=c
                bool ch = (q < 2) ? (y <= r) : (y >= r);
                bool cw = ((q & 1) == 0) ? (xx <= c) : (xx >= c);
                if (ch && cw) p = fmaxf(p, land_v[ci]);
            }
            in_s[ci_l][i][j] = p;
        }
        __syncthreads();

        // ---- compute ----
#pragma unroll 1
        for (int ci_l = 0; ci_l < CK; ++ci_l) {
#pragma unroll
            for (int dy = 0; dy < 3; ++dy) {
                float win[10];
#pragma unroll
                for (int t = 0; t < 10; ++t)
                    win[t] = in_s[ci_l][py + dy][px0 + t];
#pragma unroll
                for (int dx = 0; dx < 3; ++dx) {
#pragma unroll
                    for (int k = 0; k < 8; ++k) {
                        float wv = w_s[ci_l][dy * 3 + dx][tco * 8 + k];
#pragma unroll
                        for (int j = 0; j < 8; ++j)
                            acc[k][j] = fmaf(wv, win[dx + j], acc[k][j]);
                    }
                }
            }
        }
        __syncthreads();
    }

    // ---- epilogue: add bias, write out ----
#pragma unroll
    for (int k = 0; k < 8; ++k) {
        int co = co_base + tco * 8 + k;
        float bv = bias[co];
        float* op = out + (((size_t)b * 256 + co) << 12)
                        + ((ty0 + py) << 6) + tx0 + px0;
#pragma unroll
        for (int j = 0; j < 8; ++j)
            op[j] = acc[k][j] + bv;
    }
}

// ---------------- launch ----------------
extern "C" void kernel_launch(void* const* d_in, const int* in_sizes, int n_in,
                              void* d_out, int out_size) {
    const float* x    = (const float*)d_in[0];
    const float* w    = (const float*)d_in[1];
    const float* bias = (const float*)d_in[2];
    float* out = (float*)d_out;

    energy_argmax_kernel<<<64, 256>>>(x);

    dim3 grid(16, 4, 16);   // spatial tiles, co tiles, batch
    conv_pool_kernel<<<grid, 256>>>(x, w, bias, out);
}